// round 7
// baseline (speedup 1.0000x reference)
#include <cuda_runtime.h>
#include <cuda_bf16.h>
#include <stdint.h>
#include <math.h>

#define BB 64
#define TT 512
#define II 256
#define HH 1024
#define OO 10
#define KTOT 1280
#define NCOL 4096
#define GRID 128
#define NT 256

#define AROW 2560            // bytes per resident-A row (1280 k * 2B)
#define OFF_ALO 81920        // A-lo plane offset
#define OFF_B   163840       // B superbuffers
#define SBUF    32768        // 2 chunk-slots * (hi 8KB + lo 8KB)
#define DYN_SMEM 229376

#define SW(o) ((o) ^ (((o) >> 3) & 0x70))

// ---------------- persistent device state ----------------
__device__ __nv_bfloat16 g_Whi[NCOL * KTOT];   // [col][k], col = cta*32 + g*8 + hloc
__device__ __nv_bfloat16 g_Wlo[NCOL * KTOT];
__device__ __nv_bfloat16 g_xhi[BB * TT * II];
__device__ __nv_bfloat16 g_xlo[BB * TT * II];
__device__ __nv_bfloat16 g_hhi[2][BB * HH];
__device__ __nv_bfloat16 g_hlo[2][BB * HH];
__device__ unsigned int g_count;
__device__ volatile unsigned int g_gen;

__device__ __forceinline__ uint32_t smem_u32(const void* p) {
    uint32_t a;
    asm("{ .reg .u64 t; cvta.to.shared.u64 t, %1; cvt.u32.u64 %0, t; }" : "=r"(a) : "l"(p));
    return a;
}

#define LDSM4(r, a) \
    asm volatile("ldmatrix.sync.aligned.m8n8.x4.shared.b16 {%0,%1,%2,%3}, [%4];" \
        : "=r"((r)[0]), "=r"((r)[1]), "=r"((r)[2]), "=r"((r)[3]) : "r"(a))

#define MMA(acc, a, b0, b1) \
    asm volatile("mma.sync.aligned.m16n8k16.row.col.f32.bf16.bf16.f32 " \
        "{%0,%1,%2,%3},{%4,%5,%6,%7},{%8,%9},{%0,%1,%2,%3};" \
        : "+f"((acc)[0]), "+f"((acc)[1]), "+f"((acc)[2]), "+f"((acc)[3]) \
        : "r"((a)[0]), "r"((a)[1]), "r"((a)[2]), "r"((a)[3]), "r"(b0), "r"(b1))

#define CP_ASYNC(dst, src) \
    asm volatile("cp.async.cg.shared.global [%0], [%1], 16;" :: "r"(dst), "l"(src))
#define CP_COMMIT() asm volatile("cp.async.commit_group;" ::: "memory")
#define CP_WAIT0()  asm volatile("cp.async.wait_group 0;" ::: "memory")
#define CP_WAIT1()  asm volatile("cp.async.wait_group 1;" ::: "memory")

// ---------------- setup: split weights/input to bf16 hi/lo ----------------
__global__ void setup_kernel(const float* __restrict__ x,
                             const float* __restrict__ Wx,
                             const float* __restrict__ Wh)
{
    int gt = blockIdx.x * blockDim.x + threadIdx.x;
    int stride = gridDim.x * blockDim.x;

    for (int i = gt; i < NCOL * KTOT; i += stride) {
        int cf = i / KTOT, k = i - cf * KTOT;
        int cta = cf >> 5, r = cf & 31;
        int g = r >> 3, hj = cta * 8 + (r & 7);
        float w = (k < HH) ? Wh[(g * HH + k) * HH + hj]
                           : Wx[(g * II + (k - HH)) * HH + hj];
        __nv_bfloat16 hi = __float2bfloat16(w);
        g_Whi[i] = hi;
        g_Wlo[i] = __float2bfloat16(w - __bfloat162float(hi));
    }
    for (int i = gt; i < BB * TT * II; i += stride) {
        float v = x[i];
        __nv_bfloat16 hi = __float2bfloat16(v);
        g_xhi[i] = hi;
        g_xlo[i] = __float2bfloat16(v - __bfloat162float(hi));
    }
    for (int i = gt; i < BB * HH; i += stride) {
        g_hhi[0][i] = __float2bfloat16(0.0f);
        g_hlo[0][i] = __float2bfloat16(0.0f);
    }
}

// ---------------- persistent HMMA LSTM ----------------
__global__ __launch_bounds__(NT, 1)
void lstm_mma_kernel(const float* __restrict__ bx,
                     const float* __restrict__ bh,
                     const float* __restrict__ Wp,
                     const float* __restrict__ bp,
                     float* __restrict__ out)
{
    extern __shared__ char smem[];
    const uint32_t sb = smem_u32(smem);
    const int tid = threadIdx.x;
    const int w   = tid >> 5;
    const int l   = tid & 31;
    const int cta = blockIdx.x;
    const int col0 = cta * 32;
    const int nq = w & 3;          // batch quarter: rows nq*16..+15
    const int kh = w >> 2;         // k-split: even/odd chunk of pair

    const int la = l & 7, lb = (l >> 3) & 1, lc = l >> 4;

    // replay-safe barrier base (read before any arrive can bump gen)
    const unsigned base = g_gen;

    // A lane base addresses
    const uint32_t aB0 = sb + (uint32_t)((lb * 8 + la) * AROW);
    const uint32_t aB1 = aB0 + 16 * AROW;
    // B lane row offset (16 batch rows per warp quarter)
    const uint32_t bR0 = (uint32_t)((nq * 16 + lc * 8 + la) * 128);

    // ---- one-time: load resident A (hi+lo) ----
#pragma unroll 4
    for (int s = 0; s < 40; s++) {
        int idx = tid + s * NT;
        int hilo = idx >= 5120;
        int rem = hilo ? idx - 5120 : idx;
        int r = rem / 160, kg = rem - r * 160;
        const __nv_bfloat16* src = (hilo ? g_Wlo : g_Whi) + (col0 + r) * KTOT + kg * 8;
        uint32_t dst = sb + (hilo ? OFF_ALO : 0) + r * AROW + ((kg ^ (r & 7)) * 16);
        CP_ASYNC(dst, src);
    }
    CP_COMMIT(); CP_WAIT0();
    __syncthreads();

    // epilogue ownership (kh==0 warps do the cell update)
    const int hj = cta * 8 + (l >> 2);
    float bias[4];
#pragma unroll
    for (int g = 0; g < 4; g++) bias[g] = bh[g * HH + hj] + bx[g * HH + hj];
    float cc[4] = {0.f, 0.f, 0.f, 0.f};

    for (int t = 0; t < TT; t++) {
        const __nv_bfloat16* hsH = g_hhi[t & 1];
        const __nv_bfloat16* hsL = g_hlo[t & 1];

        // ---- prologue: stage x-only chunk pairs (16,17) and (18,19) ----
#pragma unroll
        for (int ib = 0; ib < 2; ib++) {
            uint32_t bbase = sb + OFF_B + ib * SBUF;
#pragma unroll
            for (int s = 0; s < 8; s++) {
                int gi = tid + s * NT;
                int slot = gi >> 10;
                int rem = gi & 1023;
                int hilo = rem >> 9;
                int rem2 = rem & 511;
                int n = rem2 >> 3, kg = rem2 & 7;
                int kx = (ib * 2 + slot) * 64 + kg * 8;   // within x (k-1024)
                const __nv_bfloat16* src = (hilo ? g_xlo : g_xhi) + (n * TT + t) * II + kx;
                uint32_t dst = bbase + slot * 16384 + hilo * 8192 + SW(n * 128 + kg * 16);
                CP_ASYNC(dst, src);
            }
            CP_COMMIT();
        }

        float acc[2][2][4];
#pragma unroll
        for (int mt = 0; mt < 2; mt++)
#pragma unroll
            for (int nf = 0; nf < 2; nf++)
#pragma unroll
                for (int e = 0; e < 4; e++) acc[mt][nf][e] = 0.f;

        for (int i = 0; i < 10; i++) {
            if (i == 9) { CP_WAIT0(); } else { CP_WAIT1(); }
            __syncthreads();

            // chunk order: 16,17,18,19, then 0..15
            const int chunk = (i < 2) ? (16 + 2 * i + kh) : (2 * i - 4 + kh);
            const uint32_t bufB = sb + OFF_B + (i & 1) * SBUF + kh * 16384;
#pragma unroll
            for (int ks = 0; ks < 4; ks++) {
                uint32_t ah0[4], ah1[4], al0[4], al1[4], bhf[4], blf[4];
                uint32_t aoff = (uint32_t)(((chunk * 8 + ks * 2 + lc) ^ la) * 16);
                LDSM4(ah0, aB0 + aoff);
                LDSM4(ah1, aB1 + aoff);
                LDSM4(al0, aB0 + OFF_ALO + aoff);
                LDSM4(al1, aB1 + OFF_ALO + aoff);
                uint32_t boff = (uint32_t)((((ks * 2 + lb) ^ la)) * 16);
                LDSM4(bhf, bufB + bR0 + boff);
                LDSM4(blf, bufB + 8192 + bR0 + boff);
                // pass 1: hi*hi
                MMA(acc[0][0], ah0, bhf[0], bhf[1]);
                MMA(acc[0][1], ah0, bhf[2], bhf[3]);
                MMA(acc[1][0], ah1, bhf[0], bhf[1]);
                MMA(acc[1][1], ah1, bhf[2], bhf[3]);
                // pass 2: hi*lo
                MMA(acc[0][0], ah0, blf[0], blf[1]);
                MMA(acc[0][1], ah0, blf[2], blf[3]);
                MMA(acc[1][0], ah1, blf[0], blf[1]);
                MMA(acc[1][1], ah1, blf[2], blf[3]);
                // pass 3: lo*hi
                MMA(acc[0][0], al0, bhf[0], bhf[1]);
                MMA(acc[0][1], al0, bhf[2], bhf[3]);
                MMA(acc[1][0], al1, bhf[0], bhf[1]);
                MMA(acc[1][1], al1, bhf[2], bhf[3]);
            }
            __syncthreads();

            if (i < 8) {
                if (i == 0) {
                    // grid barrier WAIT: h of step t must be fully published
                    if (tid == 0) {
                        while ((g_gen - base) < (unsigned)t) { }
                    }
                    __syncthreads();
                    __threadfence();
                }
                uint32_t bbase = sb + OFF_B + (i & 1) * SBUF;
#pragma unroll
                for (int s = 0; s < 8; s++) {
                    int gi = tid + s * NT;
                    int slot = gi >> 10;
                    int rem = gi & 1023;
                    int hilo = rem >> 9;
                    int rem2 = rem & 511;
                    int n = rem2 >> 3, kg = rem2 & 7;
                    int k = (2 * i + slot) * 64 + kg * 8;   // h chunks 0..15
                    const __nv_bfloat16* src = (hilo ? hsL : hsH) + n * HH + k;
                    uint32_t dst = bbase + slot * 16384 + hilo * 8192 + SW(n * 128 + kg * 16);
                    CP_ASYNC(dst, src);
                }
                CP_COMMIT();
            }
        }

        // ---- k-split reduction: kh==1 warps -> scratch -> kh==0 warps ----
        float* scratch = (float*)(smem + OFF_B);   // 8KB, superbuf0 region (drained)
        if (kh == 1) {
#pragma unroll
            for (int mt = 0; mt < 2; mt++)
#pragma unroll
                for (int nf = 0; nf < 2; nf++)
#pragma unroll
                    for (int e = 0; e < 4; e++)
                        scratch[nq * 512 + ((mt * 2 + nf) * 4 + e) * 32 + l] = acc[mt][nf][e];
        }
        __syncthreads();

        if (kh == 0) {
#pragma unroll
            for (int mt = 0; mt < 2; mt++)
#pragma unroll
                for (int nf = 0; nf < 2; nf++)
#pragma unroll
                    for (int e = 0; e < 4; e++)
                        acc[mt][nf][e] += scratch[nq * 512 + ((mt * 2 + nf) * 4 + e) * 32 + l];

            __nv_bfloat16* hdH = g_hhi[(t + 1) & 1];
            __nv_bfloat16* hdL = g_hlo[(t + 1) & 1];
#pragma unroll
            for (int nf = 0; nf < 2; nf++) {
#pragma unroll
                for (int par = 0; par < 2; par++) {
                    float zg = acc[0][nf][par]     + bias[0];
                    float zi = acc[0][nf][2 + par] + bias[1];
                    float zf = acc[1][nf][par]     + bias[2];
                    float zo = acc[1][nf][2 + par] + bias[3];
                    float gg = tanhf(zg);
                    float ii = 1.0f / (1.0f + __expf(-zi));
                    float ff = 1.0f / (1.0f + __expf(-zf));
                    float oo = 1.0f / (1.0f + __expf(-zo));
                    float cv = gg * ii + cc[nf * 2 + par] * ff;
                    cc[nf * 2 + par] = cv;
                    float hv = tanhf(cv) * oo;
                    int b = nq * 16 + nf * 8 + 2 * (l & 3) + par;
                    __nv_bfloat16 hi = __float2bfloat16(hv);
                    hdH[b * HH + hj] = hi;
                    hdL[b * HH + hj] = __float2bfloat16(hv - __bfloat162float(hi));
                }
            }
        }
        __syncthreads();   // h stores + scratch reads done before arrive/restage

        // grid barrier ARRIVE (wait happens next step, after x-chunk work)
        if (tid == 0) {
            __threadfence();
            if (atomicAdd(&g_count, 1u) == GRID - 1) {
                g_count = 0;
                __threadfence();
                g_gen = base + (unsigned)(t + 1);
            }
        }
    }

    // ---------- final projection + softmax (final h in buffer 0) ----------
    if (blockIdx.x < BB) {
        if (tid == 0) {
            while ((g_gen - base) < (unsigned)TT) { }
        }
        __syncthreads();
        __threadfence();

        float* red    = (float*)(smem + OFF_B);
        float* logits = red + NT;
        const int b = blockIdx.x;
        float part[OO];
#pragma unroll
        for (int o = 0; o < OO; o++) part[o] = 0.f;
        for (int k = tid; k < HH; k += NT) {
            unsigned short uh = __ldcg((const unsigned short*)&g_hhi[0][b * HH + k]);
            unsigned short ul = __ldcg((const unsigned short*)&g_hlo[0][b * HH + k]);
            float hv = __bfloat162float(__ushort_as_bfloat16(uh))
                     + __bfloat162float(__ushort_as_bfloat16(ul));
#pragma unroll
            for (int o = 0; o < OO; o++) part[o] += hv * Wp[k * OO + o];
        }
        for (int o = 0; o < OO; o++) {
            red[tid] = part[o];
            __syncthreads();
            for (int s = NT / 2; s > 0; s >>= 1) {
                if (tid < s) red[tid] += red[tid + s];
                __syncthreads();
            }
            if (tid == 0) logits[o] = red[0] + bp[o];
            __syncthreads();
        }
        if (tid == 0) {
            float m = logits[0];
#pragma unroll
            for (int o = 1; o < OO; o++) m = fmaxf(m, logits[o]);
            float s = 0.f, e[OO];
#pragma unroll
            for (int o = 0; o < OO; o++) { e[o] = expf(logits[o] - m); s += e[o]; }
            float inv = 1.0f / s;
#pragma unroll
            for (int o = 0; o < OO; o++) out[b * OO + o] = e[o] * inv;
        }
    }
}

extern "C" void kernel_launch(void* const* d_in, const int* in_sizes, int n_in,
                              void* d_out, int out_size) {
    const float* x  = (const float*)d_in[0];
    const float* Wx = (const float*)d_in[1];
    const float* bx = (const float*)d_in[2];
    const float* Wh = (const float*)d_in[3];
    const float* bh = (const float*)d_in[4];
    const float* Wp = (const float*)d_in[5];
    const float* bp = (const float*)d_in[6];
    float* out = (float*)d_out;

    cudaFuncSetAttribute(lstm_mma_kernel, cudaFuncAttributeMaxDynamicSharedMemorySize, DYN_SMEM);
    setup_kernel<<<512, 256>>>(x, Wx, Wh);
    lstm_mma_kernel<<<GRID, NT, DYN_SMEM>>>(bx, bh, Wp, bp, out);
}

// round 8
// speedup vs baseline: 1.6943x; 1.6943x over previous
#include <cuda_runtime.h>
#include <cuda_fp16.h>
#include <stdint.h>
#include <math.h>

#define BB 64
#define TT 512
#define II 256
#define HH 1024
#define OO 10
#define KTOT 1280
#define NCOL 4096
#define GRID 128
#define NT 128

#define AROW 2560            // bytes per resident-A row (1280 k * 2B fp16)
#define OFF_B 81920          // B superbuffers after 80KB resident A
#define SBUF  65536          // 4 chunk-slots * (hi 8KB + lo 8KB)
#define SLOT  16384
#define DYN_SMEM (OFF_B + 2 * SBUF)   // 212992

#define SW(o) ((o) ^ (((o) >> 3) & 0x70))

// ---------------- persistent device state ----------------
__device__ __half g_W[NCOL * KTOT];        // [col][k], col = cta*32 + g*8 + hloc
__device__ __half g_xhi[BB * TT * II];
__device__ __half g_xlo[BB * TT * II];
__device__ __half g_hhi[2][BB * HH];
__device__ __half g_hlo[2][BB * HH];
__device__ unsigned int g_count;
__device__ volatile unsigned int g_gen;

__device__ __forceinline__ uint32_t smem_u32(const void* p) {
    uint32_t a;
    asm("{ .reg .u64 t; cvta.to.shared.u64 t, %1; cvt.u32.u64 %0, t; }" : "=r"(a) : "l"(p));
    return a;
}

#define LDSM4(r, a) \
    asm volatile("ldmatrix.sync.aligned.m8n8.x4.shared.b16 {%0,%1,%2,%3}, [%4];" \
        : "=r"((r)[0]), "=r"((r)[1]), "=r"((r)[2]), "=r"((r)[3]) : "r"(a))

#define MMA(acc, a, b0, b1) \
    asm volatile("mma.sync.aligned.m16n8k16.row.col.f32.f16.f16.f32 " \
        "{%0,%1,%2,%3},{%4,%5,%6,%7},{%8,%9},{%0,%1,%2,%3};" \
        : "+f"((acc)[0]), "+f"((acc)[1]), "+f"((acc)[2]), "+f"((acc)[3]) \
        : "r"((a)[0]), "r"((a)[1]), "r"((a)[2]), "r"((a)[3]), "r"(b0), "r"(b1))

#define CP_ASYNC(dst, src) \
    asm volatile("cp.async.cg.shared.global [%0], [%1], 16;" :: "r"(dst), "l"(src))
#define CP_COMMIT() asm volatile("cp.async.commit_group;" ::: "memory")
#define CP_WAIT0()  asm volatile("cp.async.wait_group 0;" ::: "memory")
#define CP_WAIT1()  asm volatile("cp.async.wait_group 1;" ::: "memory")

// ---------------- setup ----------------
__global__ void setup_kernel(const float* __restrict__ x,
                             const float* __restrict__ Wx,
                             const float* __restrict__ Wh)
{
    int gt = blockIdx.x * blockDim.x + threadIdx.x;
    int stride = gridDim.x * blockDim.x;

    for (int i = gt; i < NCOL * KTOT; i += stride) {
        int cf = i / KTOT, k = i - cf * KTOT;
        int cta = cf >> 5, r = cf & 31;
        int g = r >> 3, hj = cta * 8 + (r & 7);
        float w = (k < HH) ? Wh[(g * HH + k) * HH + hj]
                           : Wx[(g * II + (k - HH)) * HH + hj];
        g_W[i] = __float2half(w);
    }
    for (int i = gt; i < BB * TT * II; i += stride) {
        float v = x[i];
        __half hi = __float2half(v);
        g_xhi[i] = hi;
        g_xlo[i] = __float2half(v - __half2float(hi));
    }
    for (int i = gt; i < BB * HH; i += stride) {
        g_hhi[0][i] = __float2half(0.0f);
        g_hlo[0][i] = __float2half(0.0f);
    }
}

// ---------------- persistent HMMA LSTM, fp16 2-pass ----------------
__global__ __launch_bounds__(NT, 1)
void lstm_mma_kernel(const float* __restrict__ bx,
                     const float* __restrict__ bh,
                     const float* __restrict__ Wp,
                     const float* __restrict__ bp,
                     float* __restrict__ out)
{
    extern __shared__ char smem[];
    const uint32_t sb = smem_u32(smem);
    const int tid = threadIdx.x;
    const int w   = tid >> 5;
    const int l   = tid & 31;
    const int cta = blockIdx.x;
    const int col0 = cta * 32;
    const int nh = w & 1;          // batch half: rows nh*32..+31
    const int kh = w >> 1;         // k-split: slots {0,1} vs {2,3}

    const int la = l & 7, lb = (l >> 3) & 1, lc = l >> 4;

    const unsigned base = g_gen;   // replay-safe barrier base

    // A lane base addresses (resident fp16 plane)
    const uint32_t aB0 = sb + (uint32_t)((lb * 8 + la) * AROW);
    const uint32_t aB1 = aB0 + 16 * AROW;
    // B lane row offset within a chunk slot
    const uint32_t bR0 = (uint32_t)((nh * 32 + lc * 8 + la) * 128);

    // ---- one-time: load resident A (80KB fp16) ----
#pragma unroll 4
    for (int s = 0; s < 40; s++) {
        int idx = tid + s * NT;
        int r = idx / 160, kg = idx - r * 160;
        const __half* src = g_W + (col0 + r) * KTOT + kg * 8;
        uint32_t dst = sb + r * AROW + ((kg ^ (r & 7)) * 16);
        CP_ASYNC(dst, src);
    }
    CP_COMMIT(); CP_WAIT0();
    __syncthreads();

    // epilogue ownership (kh==0 warps)
    const int hj = cta * 8 + (l >> 2);
    float bias[4];
#pragma unroll
    for (int g = 0; g < 4; g++) bias[g] = bh[g * HH + hj] + bx[g * HH + hj];
    float cc[8];
#pragma unroll
    for (int q = 0; q < 8; q++) cc[q] = 0.f;

    for (int t = 0; t < TT; t++) {
        const __half* hsH = g_hhi[t & 1];
        const __half* hsL = g_hlo[t & 1];

        // ---- prologue: stage iter0 = x chunks 16..19 into superbuf0 ----
        {
            uint32_t bbase = sb + OFF_B;
#pragma unroll
            for (int s = 0; s < 32; s++) {
                int gi = tid + s * NT;
                int slot = gi >> 10;
                int rem = gi & 1023;
                int hilo = rem >> 9;
                int rem2 = rem & 511;
                int n = rem2 >> 3, kg = rem2 & 7;
                int kx = slot * 64 + kg * 8;      // within x part
                const __half* src = (hilo ? g_xlo : g_xhi) + (n * TT + t) * II + kx;
                uint32_t dst = bbase + slot * SLOT + hilo * 8192 + SW(n * 128 + kg * 16);
                CP_ASYNC(dst, src);
            }
            CP_COMMIT();
        }

        // grid barrier WAIT (h of step t published) — overlaps x transfer
        if (tid == 0) {
            while ((g_gen - base) < (unsigned)t) { }
        }
        __syncthreads();
        __threadfence();

        // stage iter1 = h chunks 0..3 into superbuf1
        {
            uint32_t bbase = sb + OFF_B + SBUF;
#pragma unroll
            for (int s = 0; s < 32; s++) {
                int gi = tid + s * NT;
                int slot = gi >> 10;
                int rem = gi & 1023;
                int hilo = rem >> 9;
                int rem2 = rem & 511;
                int n = rem2 >> 3, kg = rem2 & 7;
                int k = slot * 64 + kg * 8;
                const __half* src = (hilo ? hsL : hsH) + n * HH + k;
                uint32_t dst = bbase + slot * SLOT + hilo * 8192 + SW(n * 128 + kg * 16);
                CP_ASYNC(dst, src);
            }
            CP_COMMIT();
        }

        float acc[2][4][4];
#pragma unroll
        for (int mt = 0; mt < 2; mt++)
#pragma unroll
            for (int nf = 0; nf < 4; nf++)
#pragma unroll
                for (int e = 0; e < 4; e++) acc[mt][nf][e] = 0.f;

        for (int i = 0; i < 5; i++) {
            if (i == 4) { CP_WAIT0(); } else { CP_WAIT1(); }
            __syncthreads();

            const uint32_t bufB = sb + OFF_B + (i & 1) * SBUF;
#pragma unroll
            for (int cw = 0; cw < 2; cw++) {
                const int sl = kh * 2 + cw;
                const int chunk = (i == 0) ? (16 + sl) : ((i - 1) * 4 + sl);
                const uint32_t slotB = bufB + sl * SLOT;
#pragma unroll
                for (int ks = 0; ks < 4; ks++) {
                    uint32_t ah0[4], ah1[4], bhf[8], blf[8];
                    uint32_t aoff = (uint32_t)(((chunk * 8 + ks * 2 + lc) ^ la) * 16);
                    LDSM4(ah0, aB0 + aoff);
                    LDSM4(ah1, aB1 + aoff);
                    uint32_t boff = (uint32_t)(((ks * 2 + lb) ^ la) * 16);
                    LDSM4(bhf,     slotB + bR0 + boff);
                    LDSM4(bhf + 4, slotB + bR0 + 2048 + boff);
                    LDSM4(blf,     slotB + 8192 + bR0 + boff);
                    LDSM4(blf + 4, slotB + 8192 + bR0 + 2048 + boff);
                    // pass 1: W * b_hi
                    MMA(acc[0][0], ah0, bhf[0], bhf[1]);
                    MMA(acc[0][1], ah0, bhf[2], bhf[3]);
                    MMA(acc[0][2], ah0, bhf[4], bhf[5]);
                    MMA(acc[0][3], ah0, bhf[6], bhf[7]);
                    MMA(acc[1][0], ah1, bhf[0], bhf[1]);
                    MMA(acc[1][1], ah1, bhf[2], bhf[3]);
                    MMA(acc[1][2], ah1, bhf[4], bhf[5]);
                    MMA(acc[1][3], ah1, bhf[6], bhf[7]);
                    // pass 2: W * b_lo
                    MMA(acc[0][0], ah0, blf[0], blf[1]);
                    MMA(acc[0][1], ah0, blf[2], blf[3]);
                    MMA(acc[0][2], ah0, blf[4], blf[5]);
                    MMA(acc[0][3], ah0, blf[6], blf[7]);
                    MMA(acc[1][0], ah1, blf[0], blf[1]);
                    MMA(acc[1][1], ah1, blf[2], blf[3]);
                    MMA(acc[1][2], ah1, blf[4], blf[5]);
                    MMA(acc[1][3], ah1, blf[6], blf[7]);
                }
            }
            __syncthreads();

            // stage iter i+2 into buffer (i&1): h chunks (i+1)*4 .. +3
            if (i + 2 < 5) {
                uint32_t bbase = sb + OFF_B + (i & 1) * SBUF;
                int c0 = (i + 1) * 4;
#pragma unroll
                for (int s = 0; s < 32; s++) {
                    int gi = tid + s * NT;
                    int slot = gi >> 10;
                    int rem = gi & 1023;
                    int hilo = rem >> 9;
                    int rem2 = rem & 511;
                    int n = rem2 >> 3, kg = rem2 & 7;
                    int k = (c0 + slot) * 64 + kg * 8;
                    const __half* src = (hilo ? hsL : hsH) + n * HH + k;
                    uint32_t dst = bbase + slot * SLOT + hilo * 8192 + SW(n * 128 + kg * 16);
                    CP_ASYNC(dst, src);
                }
                CP_COMMIT();
            }
        }

        // ---- k-split reduction: kh==1 warps -> scratch -> kh==0 warps ----
        float* scratch = (float*)(smem + OFF_B);   // superbuf0 drained
        if (kh == 1) {
#pragma unroll
            for (int mt = 0; mt < 2; mt++)
#pragma unroll
                for (int nf = 0; nf < 4; nf++)
#pragma unroll
                    for (int e = 0; e < 4; e++)
                        scratch[nh * 1024 + ((mt * 4 + nf) * 4 + e) * 32 + l] = acc[mt][nf][e];
        }
        __syncthreads();

        if (kh == 0) {
#pragma unroll
            for (int mt = 0; mt < 2; mt++)
#pragma unroll
                for (int nf = 0; nf < 4; nf++)
#pragma unroll
                    for (int e = 0; e < 4; e++)
                        acc[mt][nf][e] += scratch[nh * 1024 + ((mt * 4 + nf) * 4 + e) * 32 + l];

            __half* hdH = g_hhi[(t + 1) & 1];
            __half* hdL = g_hlo[(t + 1) & 1];
#pragma unroll
            for (int nf = 0; nf < 4; nf++) {
#pragma unroll
                for (int par = 0; par < 2; par++) {
                    float zg = acc[0][nf][par]     + bias[0];
                    float zi = acc[0][nf][2 + par] + bias[1];
                    float zf = acc[1][nf][par]     + bias[2];
                    float zo = acc[1][nf][2 + par] + bias[3];
                    float gg = tanhf(zg);
                    float ii = 1.0f / (1.0f + __expf(-zi));
                    float ff = 1.0f / (1.0f + __expf(-zf));
                    float oo = 1.0f / (1.0f + __expf(-zo));
                    float cv = gg * ii + cc[nf * 2 + par] * ff;
                    cc[nf * 2 + par] = cv;
                    float hv = tanhf(cv) * oo;
                    int b = nh * 32 + nf * 8 + 2 * (l & 3) + par;
                    __half hi = __float2half(hv);
                    hdH[b * HH + hj] = hi;
                    hdL[b * HH + hj] = __float2half(hv - __half2float(hi));
                }
            }
        }
        __syncthreads();   // h stores + scratch reads complete

        // grid barrier ARRIVE
        if (tid == 0) {
            __threadfence();
            if (atomicAdd(&g_count, 1u) == GRID - 1) {
                g_count = 0;
                __threadfence();
                g_gen = base + (unsigned)(t + 1);
            }
        }
    }

    // ---------- final projection + softmax (final h in buffer 0) ----------
    if (blockIdx.x < BB) {
        if (tid == 0) {
            while ((g_gen - base) < (unsigned)TT) { }
        }
        __syncthreads();
        __threadfence();

        float* red    = (float*)(smem + OFF_B);
        float* logits = red + NT;
        const int b = blockIdx.x;
        float part[OO];
#pragma unroll
        for (int o = 0; o < OO; o++) part[o] = 0.f;
        for (int k = tid; k < HH; k += NT) {
            unsigned short uh = __ldcg((const unsigned short*)&g_hhi[0][b * HH + k]);
            unsigned short ul = __ldcg((const unsigned short*)&g_hlo[0][b * HH + k]);
            float hv = __half2float(__ushort_as_half(uh))
                     + __half2float(__ushort_as_half(ul));
#pragma unroll
            for (int o = 0; o < OO; o++) part[o] += hv * Wp[k * OO + o];
        }
        for (int o = 0; o < OO; o++) {
            red[tid] = part[o];
            __syncthreads();
            for (int s = NT / 2; s > 0; s >>= 1) {
                if (tid < s) red[tid] += red[tid + s];
                __syncthreads();
            }
            if (tid == 0) logits[o] = red[0] + bp[o];
            __syncthreads();
        }
        if (tid == 0) {
            float m = logits[0];
#pragma unroll
            for (int o = 1; o < OO; o++) m = fmaxf(m, logits[o]);
            float s = 0.f, e[OO];
#pragma unroll
            for (int o = 0; o < OO; o++) { e[o] = expf(logits[o] - m); s += e[o]; }
            float inv = 1.0f / s;
#pragma unroll
            for (int o = 0; o < OO; o++) out[b * OO + o] = e[o] * inv;
        }
    }
}

extern "C" void kernel_launch(void* const* d_in, const int* in_sizes, int n_in,
                              void* d_out, int out_size) {
    const float* x  = (const float*)d_in[0];
    const float* Wx = (const float*)d_in[1];
    const float* bx = (const float*)d_in[2];
    const float* Wh = (const float*)d_in[3];
    const float* bh = (const float*)d_in[4];
    const float* Wp = (const float*)d_in[5];
    const float* bp = (const float*)d_in[6];
    float* out = (float*)d_out;

    cudaFuncSetAttribute(lstm_mma_kernel, cudaFuncAttributeMaxDynamicSharedMemorySize, DYN_SMEM);
    setup_kernel<<<512, 256>>>(x, Wx, Wh);
    lstm_mma_kernel<<<GRID, NT, DYN_SMEM>>>(bx, bh, Wp, bp, out);
}

// round 9
// speedup vs baseline: 2.2367x; 1.3201x over previous
#include <cuda_runtime.h>
#include <cuda_fp16.h>
#include <stdint.h>
#include <math.h>

#define BB 64
#define TT 512
#define II 256
#define HH 1024
#define OO 10
#define KTOT 1280
#define NCOL 4096
#define GRID 128
#define NT 256

#define AROW 2560            // bytes per resident-A row (1280 k * 2B fp16)
#define OFF_B 81920          // B superbuffers after 80KB resident A
#define SBUF  32768          // 4 chunk-slots * 8KB (single fp16 plane)
#define SLOT  8192
#define DYN_SMEM (OFF_B + 2 * SBUF)   // 147456

#define SW(o) ((o) ^ (((o) >> 3) & 0x70))

// ---------------- persistent device state ----------------
__device__ __half g_W[NCOL * KTOT];        // [col][k], col = cta*32 + g*8 + hloc
__device__ __half g_x[BB * TT * II];
__device__ __half g_h[2][BB * HH];
__device__ unsigned int g_count;
__device__ volatile unsigned int g_gen;

__device__ __forceinline__ uint32_t smem_u32(const void* p) {
    uint32_t a;
    asm("{ .reg .u64 t; cvta.to.shared.u64 t, %1; cvt.u32.u64 %0, t; }" : "=r"(a) : "l"(p));
    return a;
}

#define LDSM4(r, a) \
    asm volatile("ldmatrix.sync.aligned.m8n8.x4.shared.b16 {%0,%1,%2,%3}, [%4];" \
        : "=r"((r)[0]), "=r"((r)[1]), "=r"((r)[2]), "=r"((r)[3]) : "r"(a))

#define MMA(acc, a, b0, b1) \
    asm volatile("mma.sync.aligned.m16n8k16.row.col.f32.f16.f16.f32 " \
        "{%0,%1,%2,%3},{%4,%5,%6,%7},{%8,%9},{%0,%1,%2,%3};" \
        : "+f"((acc)[0]), "+f"((acc)[1]), "+f"((acc)[2]), "+f"((acc)[3]) \
        : "r"((a)[0]), "r"((a)[1]), "r"((a)[2]), "r"((a)[3]), "r"(b0), "r"(b1))

#define CP_ASYNC(dst, src) \
    asm volatile("cp.async.cg.shared.global [%0], [%1], 16;" :: "r"(dst), "l"(src))
#define CP_COMMIT() asm volatile("cp.async.commit_group;" ::: "memory")
#define CP_WAIT0()  asm volatile("cp.async.wait_group 0;" ::: "memory")
#define CP_WAIT1()  asm volatile("cp.async.wait_group 1;" ::: "memory")

// ---------------- setup ----------------
__global__ void setup_kernel(const float* __restrict__ x,
                             const float* __restrict__ Wx,
                             const float* __restrict__ Wh)
{
    int gt = blockIdx.x * blockDim.x + threadIdx.x;
    int stride = gridDim.x * blockDim.x;

    for (int i = gt; i < NCOL * KTOT; i += stride) {
        int cf = i / KTOT, k = i - cf * KTOT;
        int cta = cf >> 5, r = cf & 31;
        int g = r >> 3, hj = cta * 8 + (r & 7);
        float w = (k < HH) ? Wh[(g * HH + k) * HH + hj]
                           : Wx[(g * II + (k - HH)) * HH + hj];
        g_W[i] = __float2half(w);
    }
    for (int i = gt; i < BB * TT * II; i += stride)
        g_x[i] = __float2half(x[i]);
    for (int i = gt; i < BB * HH; i += stride)
        g_h[0][i] = __float2half(0.0f);
}

// ---------------- persistent HMMA LSTM, fp16 1-pass, 8 warps ----------------
__global__ __launch_bounds__(NT, 1)
void lstm_mma_kernel(const float* __restrict__ bx,
                     const float* __restrict__ bh,
                     const float* __restrict__ Wp,
                     const float* __restrict__ bp,
                     float* __restrict__ out)
{
    extern __shared__ char smem[];
    const uint32_t sb = smem_u32(smem);
    const int tid = threadIdx.x;
    const int w   = tid >> 5;
    const int l   = tid & 31;
    const int cta = blockIdx.x;
    const int col0 = cta * 32;
    const int nh = w & 1;          // batch half: rows nh*32..+31
    const int kh = w >> 1;         // k-split quarter: 0..3

    const int la = l & 7, lb = (l >> 3) & 1, lc = l >> 4;

    const unsigned base = g_gen;   // replay-safe barrier base

    // A lane base addresses (resident fp16 plane)
    const uint32_t aB0 = sb + (uint32_t)((lb * 8 + la) * AROW);
    const uint32_t aB1 = aB0 + 16 * AROW;
    // B lane row offset within a chunk slot
    const uint32_t bR0 = (uint32_t)((nh * 32 + lc * 8 + la) * 128);

    // ---- one-time: load resident A (80KB fp16) ----
#pragma unroll 4
    for (int s = 0; s < 20; s++) {
        int idx = tid + s * NT;
        int r = idx / 160, kg = idx - r * 160;
        const __half* src = g_W + (col0 + r) * KTOT + kg * 8;
        uint32_t dst = sb + r * AROW + ((kg ^ (r & 7)) * 16);
        CP_ASYNC(dst, src);
    }
    CP_COMMIT(); CP_WAIT0();
    __syncthreads();

    // epilogue ownership (kh==0 warps)
    const int hj = cta * 8 + (l >> 2);
    float bias[4];
#pragma unroll
    for (int g = 0; g < 4; g++) bias[g] = bh[g * HH + hj] + bx[g * HH + hj];
    float cc[8];
#pragma unroll
    for (int q = 0; q < 8; q++) cc[q] = 0.f;

    for (int t = 0; t < TT; t++) {
        const __half* hs = g_h[t & 1];

        // ---- prologue: stage iter0 = x chunks 16..19 into superbuf0 ----
        {
            uint32_t bbase = sb + OFF_B;
#pragma unroll
            for (int s = 0; s < 8; s++) {
                int gi = tid + s * NT;
                int slot = gi >> 9;
                int rem = gi & 511;
                int n = rem >> 3, kg = rem & 7;
                int kx = slot * 64 + kg * 8;
                const __half* src = g_x + (n * TT + t) * II + kx;
                uint32_t dst = bbase + slot * SLOT + SW(n * 128 + kg * 16);
                CP_ASYNC(dst, src);
            }
            CP_COMMIT();
        }

        // grid barrier WAIT (h of step t published) — overlaps x transfer
        if (tid == 0) {
            while ((g_gen - base) < (unsigned)t) { }
        }
        __syncthreads();
        __threadfence();

        // stage iter1 = h chunks 0..3 into superbuf1
        {
            uint32_t bbase = sb + OFF_B + SBUF;
#pragma unroll
            for (int s = 0; s < 8; s++) {
                int gi = tid + s * NT;
                int slot = gi >> 9;
                int rem = gi & 511;
                int n = rem >> 3, kg = rem & 7;
                int k = slot * 64 + kg * 8;
                const __half* src = hs + n * HH + k;
                uint32_t dst = bbase + slot * SLOT + SW(n * 128 + kg * 16);
                CP_ASYNC(dst, src);
            }
            CP_COMMIT();
        }

        float acc[2][4][4];
#pragma unroll
        for (int mt = 0; mt < 2; mt++)
#pragma unroll
            for (int nf = 0; nf < 4; nf++)
#pragma unroll
                for (int e = 0; e < 4; e++) acc[mt][nf][e] = 0.f;

        for (int i = 0; i < 5; i++) {
            if (i == 4) { CP_WAIT0(); } else { CP_WAIT1(); }
            __syncthreads();

            const int chunk = (i == 0) ? (16 + kh) : ((i - 1) * 4 + kh);
            const uint32_t slotB = sb + OFF_B + (i & 1) * SBUF + kh * SLOT;
#pragma unroll
            for (int ks = 0; ks < 4; ks++) {
                uint32_t ah0[4], ah1[4], bhf[8];
                uint32_t aoff = (uint32_t)(((chunk * 8 + ks * 2 + lc) ^ la) * 16);
                LDSM4(ah0, aB0 + aoff);
                LDSM4(ah1, aB1 + aoff);
                uint32_t boff = (uint32_t)(((ks * 2 + lb) ^ la) * 16);
                LDSM4(bhf,     slotB + bR0 + boff);
                LDSM4(bhf + 4, slotB + bR0 + 2048 + boff);
                MMA(acc[0][0], ah0, bhf[0], bhf[1]);
                MMA(acc[0][1], ah0, bhf[2], bhf[3]);
                MMA(acc[0][2], ah0, bhf[4], bhf[5]);
                MMA(acc[0][3], ah0, bhf[6], bhf[7]);
                MMA(acc[1][0], ah1, bhf[0], bhf[1]);
                MMA(acc[1][1], ah1, bhf[2], bhf[3]);
                MMA(acc[1][2], ah1, bhf[4], bhf[5]);
                MMA(acc[1][3], ah1, bhf[6], bhf[7]);
            }
            __syncthreads();

            // stage iter i+2 into buffer (i&1): h chunks (i+1)*4 .. +3
            if (i + 2 < 5) {
                uint32_t bbase = sb + OFF_B + (i & 1) * SBUF;
                int c0 = (i + 1) * 4;
#pragma unroll
                for (int s = 0; s < 8; s++) {
                    int gi = tid + s * NT;
                    int slot = gi >> 9;
                    int rem = gi & 511;
                    int n = rem >> 3, kg = rem & 7;
                    int k = (c0 + slot) * 64 + kg * 8;
                    const __half* src = hs + n * HH + k;
                    uint32_t dst = bbase + slot * SLOT + SW(n * 128 + kg * 16);
                    CP_ASYNC(dst, src);
                }
                CP_COMMIT();
            }
        }

        // ---- 4-way k-split reduction: kh 1..3 -> scratch -> kh==0 ----
        float* scratch = (float*)(smem + OFF_B);   // both superbufs drained (48KB used)
        if (kh != 0) {
            float* dst = scratch + ((kh - 1) * 2 + nh) * 1024;
#pragma unroll
            for (int mt = 0; mt < 2; mt++)
#pragma unroll
                for (int nf = 0; nf < 4; nf++)
#pragma unroll
                    for (int e = 0; e < 4; e++)
                        dst[((mt * 4 + nf) * 4 + e) * 32 + l] = acc[mt][nf][e];
        }
        __syncthreads();

        if (kh == 0) {
#pragma unroll
            for (int q = 1; q < 4; q++) {
                const float* src = scratch + ((q - 1) * 2 + nh) * 1024;
#pragma unroll
                for (int mt = 0; mt < 2; mt++)
#pragma unroll
                    for (int nf = 0; nf < 4; nf++)
#pragma unroll
                        for (int e = 0; e < 4; e++)
                            acc[mt][nf][e] += src[((mt * 4 + nf) * 4 + e) * 32 + l];
            }

            __half* hd = g_h[(t + 1) & 1];
#pragma unroll
            for (int nf = 0; nf < 4; nf++) {
#pragma unroll
                for (int par = 0; par < 2; par++) {
                    float zg = acc[0][nf][par]     + bias[0];
                    float zi = acc[0][nf][2 + par] + bias[1];
                    float zf = acc[1][nf][par]     + bias[2];
                    float zo = acc[1][nf][2 + par] + bias[3];
                    float gg = tanhf(zg);
                    float ii = 1.0f / (1.0f + __expf(-zi));
                    float ff = 1.0f / (1.0f + __expf(-zf));
                    float oo = 1.0f / (1.0f + __expf(-zo));
                    float cv = gg * ii + cc[nf * 2 + par] * ff;
                    cc[nf * 2 + par] = cv;
                    float hv = tanhf(cv) * oo;
                    int b = nh * 32 + nf * 8 + 2 * (l & 3) + par;
                    hd[b * HH + hj] = __float2half(hv);
                }
            }
        }
        __syncthreads();   // h stores + scratch reads complete

        // grid barrier ARRIVE
        if (tid == 0) {
            __threadfence();
            if (atomicAdd(&g_count, 1u) == GRID - 1) {
                g_count = 0;
                __threadfence();
                g_gen = base + (unsigned)(t + 1);
            }
        }
    }

    // ---------- final projection + softmax (final h in buffer 0) ----------
    if (blockIdx.x < BB) {
        if (tid == 0) {
            while ((g_gen - base) < (unsigned)TT) { }
        }
        __syncthreads();
        __threadfence();

        float* red    = (float*)(smem + OFF_B);
        float* logits = red + NT;
        const int b = blockIdx.x;
        float part[OO];
#pragma unroll
        for (int o = 0; o < OO; o++) part[o] = 0.f;
        for (int k = tid; k < HH; k += NT) {
            unsigned short uh = __ldcg((const unsigned short*)&g_h[0][b * HH + k]);
            float hv = __half2float(__ushort_as_half(uh));
#pragma unroll
            for (int o = 0; o < OO; o++) part[o] += hv * Wp[k * OO + o];
        }
        for (int o = 0; o < OO; o++) {
            red[tid] = part[o];
            __syncthreads();
            for (int s = NT / 2; s > 0; s >>= 1) {
                if (tid < s) red[tid] += red[tid + s];
                __syncthreads();
            }
            if (tid == 0) logits[o] = red[0] + bp[o];
            __syncthreads();
        }
        if (tid == 0) {
            float m = logits[0];
#pragma unroll
            for (int o = 1; o < OO; o++) m = fmaxf(m, logits[o]);
            float s = 0.f, e[OO];
#pragma unroll
            for (int o = 0; o < OO; o++) { e[o] = expf(logits[o] - m); s += e[o]; }
            float inv = 1.0f / s;
#pragma unroll
            for (int o = 0; o < OO; o++) out[b * OO + o] = e[o] * inv;
        }
    }
}

extern "C" void kernel_launch(void* const* d_in, const int* in_sizes, int n_in,
                              void* d_out, int out_size) {
    const float* x  = (const float*)d_in[0];
    const float* Wx = (const float*)d_in[1];
    const float* bx = (const float*)d_in[2];
    const float* Wh = (const float*)d_in[3];
    const float* bh = (const float*)d_in[4];
    const float* Wp = (const float*)d_in[5];
    const float* bp = (const float*)d_in[6];
    float* out = (float*)d_out;

    cudaFuncSetAttribute(lstm_mma_kernel, cudaFuncAttributeMaxDynamicSharedMemorySize, DYN_SMEM);
    setup_kernel<<<512, 256>>>(x, Wx, Wh);
    lstm_mma_kernel<<<GRID, NT, DYN_SMEM>>>(bx, bh, Wp, bp, out);
}